// round 15
// baseline (speedup 1.0000x reference)
#include <cuda_runtime.h>
#include <cuda_bf16.h>

#define NBIN 25
#define INV_DELTA 12.0f          // (NBIN-1)/2
#define GRIDX 74                 // blocks per batch
#define NBATCH 16
#define TOTAL_BLOCKS (GRIDX * NBATCH)

// Per-(batch, block) partials; fully written by owner block each launch -> no zeroing.
__device__ float gp_num[NBATCH][GRIDX][32];
__device__ float gp_den[NBATCH][GRIDX][32];
__device__ float gp_lab[NBATCH][GRIDX];
// Completion counter: atomicInc with limit TOTAL_BLOCKS-1 wraps to 0 after the last
// block -> automatically reset for every graph replay.
__device__ unsigned g_ctr = 0;

// min 6 blocks/SM caps regs at 42: hot loop fits, run-once epilogue may spill (harmless).
__global__ __launch_bounds__(256, 6) void qap_main_kernel(
    const float* __restrict__ qX,
    const float* __restrict__ dXs,
    const int* __restrict__ labels,
    int N, float* __restrict__ out)
{
    __shared__ float4 s_q[32];
    __shared__ float  s_num[8][32];
    __shared__ float  s_den[8][32];
    __shared__ float  s_lab[8];
    __shared__ int    s_last;
    __shared__ float  s_ap[NBATCH];

    const int b    = blockIdx.y;
    const int tid  = threadIdx.x;
    const int lane = tid & 31;
    const int warp = tid >> 5;
    const int g    = lane >> 2;   // row-within-chunk 0..7
    const int s    = lane & 3;    // quarter-group sub-lane 0..3

    if (tid < 32) s_q[tid] = reinterpret_cast<const float4*>(qX + (long)b * 128)[tid];
    __syncthreads();

    // ||q||^2 (identical summation order on every thread)
    float qq = 0.0f;
    #pragma unroll
    for (int i = 0; i < 32; i++) {
        float4 v = s_q[i];
        qq += v.x * v.x + v.y * v.y + v.z * v.z + v.w * v.w;
    }
    const float qinv = 1.0f / fmaxf(sqrtf(qq), 1e-8f);

    const float4* __restrict__ dbase =
        reinterpret_cast<const float4*>(dXs) + ((long)b * N) * 32;
    const int* __restrict__ lab_b = labels + (long)b * N;

    const int warps_per_b = GRIDX * 8;
    const int wid = blockIdx.x * 8 + warp;
    const int nchunks = N >> 3;           // 8-row chunks of 4KB
    const float lane_f = (float)lane;

    float num_acc = 0.0f, den_acc = 0.0f, lab_acc = 0.0f;

    // === R9 main loop (known-best memory behavior), unchanged ===
    for (int c = wid; c < nchunks; c += warps_per_b) {
        const long row = (long)c * 8 + g;
        const float4* __restrict__ rp = dbase + row * 32 + s;

        // 8 independent strided loads (chunk = 4KB contiguous, fully coalesced)
        float4 d[8];
        #pragma unroll
        for (int i = 0; i < 8; i++) d[i] = rp[4 * i];

        // label for this group's row (lanes 0,4,...,28 -> 8 consecutive ints)
        int li = 0;
        if (s == 0) li = lab_b[row];

        float dot = 0.0f, dd = 0.0f;
        #pragma unroll
        for (int i = 0; i < 8; i++) {
            float4 qi = s_q[s + 4 * i];
            dot += d[i].x * qi.x + d[i].y * qi.y + d[i].z * qi.z + d[i].w * qi.w;
            dd  += d[i].x * d[i].x + d[i].y * d[i].y + d[i].z * d[i].z + d[i].w * d[i].w;
        }

        // reduce within group of 4 lanes (2 stages, 4 shuffles per 8 rows)
        dot += __shfl_xor_sync(0xFFFFFFFFu, dot, 1);
        dd  += __shfl_xor_sync(0xFFFFFFFFu, dd,  1);
        dot += __shfl_xor_sync(0xFFFFFFFFu, dot, 2);
        dd  += __shfl_xor_sync(0xFFFFFFFFu, dd,  2);

        // sim -> bin position t in [0,24]; pack label into sign bit (t==0 safe: -0.0)
        float sim = dot * qinv * rsqrtf(fmaxf(dd, 1e-16f));
        float t = fminf(fmaxf((1.0f - sim) * INV_DELTA, 0.0f), 24.0f);
        float u = __uint_as_float(__float_as_uint(t) | (((unsigned)li) << 31));

        // 8 broadcasts: whole warp applies triangular weights; lane owns bin lane.
        #pragma unroll
        for (int j = 0; j < 8; j++) {
            float uj = __shfl_sync(0xFFFFFFFFu, u, j * 4);
            unsigned ub = __float_as_uint(uj);
            float tj = __uint_as_float(ub & 0x7FFFFFFFu);
            float lj = (float)(ub >> 31);
            float w = fmaxf(1.0f - fabsf(tj - lane_f), 0.0f);
            den_acc += w;
            num_acc += w * lj;
            lab_acc += lj;
        }
    }

    // Tail rows (N % 8): warp-per-row on warp 0 (dead for N=50000)
    if ((N & 7) && wid == 0) {
        float4 qv = s_q[lane];
        for (long r = (long)nchunks * 8; r < N; r++) {
            float4 dv = dbase[r * 32 + lane];
            float dot = dv.x * qv.x + dv.y * qv.y + dv.z * qv.z + dv.w * qv.w;
            float dd  = dv.x * dv.x + dv.y * dv.y + dv.z * dv.z + dv.w * dv.w;
            #pragma unroll
            for (int o = 16; o; o >>= 1) {
                dot += __shfl_xor_sync(0xFFFFFFFFu, dot, o);
                dd  += __shfl_xor_sync(0xFFFFFFFFu, dd,  o);
            }
            float lbl = (float)lab_b[r];
            float sim = dot * qinv * rsqrtf(fmaxf(dd, 1e-16f));
            float t = fminf(fmaxf((1.0f - sim) * INV_DELTA, 0.0f), 24.0f);
            float w = fmaxf(1.0f - fabsf(t - lane_f), 0.0f);
            den_acc += w; num_acc += w * lbl; lab_acc += lbl;
        }
    }

    // Block reduction of per-warp partials (deterministic, no atomics).
    s_num[warp][lane] = num_acc;
    s_den[warp][lane] = den_acc;
    if (lane == 0) s_lab[warp] = lab_acc;
    __syncthreads();

    if (warp == 0) {
        float n = 0.0f, dsum = 0.0f;
        #pragma unroll
        for (int w2 = 0; w2 < 8; w2++) { n += s_num[w2][lane]; dsum += s_den[w2][lane]; }
        gp_num[b][blockIdx.x][lane] = n;
        gp_den[b][blockIdx.x][lane] = dsum;
        if (lane == 0) {
            float L = 0.0f;
            #pragma unroll
            for (int w2 = 0; w2 < 8; w2++) L += s_lab[w2];
            gp_lab[b][blockIdx.x] = L;
        }
        __threadfence();   // publish gp stores before signaling
    }
    __syncthreads();

    if (tid == 0) {
        unsigned rank = atomicInc(&g_ctr, TOTAL_BLOCKS - 1);  // wraps -> replay-safe
        s_last = (rank == TOTAL_BLOCKS - 1);
    }
    __syncthreads();
    if (!s_last) return;

    // ---- Last block: finalize (reads hit L2; runs once, spills harmless) ----
    __threadfence();  // acquire side
    const int b0 = warp * 2;
    const int b1 = b0 + 1;
    float n0 = 0.f, d0 = 0.f, L0 = 0.f, n1 = 0.f, d1 = 0.f, L1 = 0.f;
    #pragma unroll 2
    for (int jj = 0; jj < GRIDX; jj++) {   // 6 interleaved load streams -> MLP
        n0 += gp_num[b0][jj][lane];  n1 += gp_num[b1][jj][lane];
        d0 += gp_den[b0][jj][lane];  d1 += gp_den[b1][jj][lane];
        L0 += gp_lab[b0][jj];        L1 += gp_lab[b1][jj];
    }

    #pragma unroll
    for (int pass = 0; pass < 2; pass++) {
        float n = pass ? n1 : n0, d = pass ? d1 : d0, L = pass ? L1 : L0;
        float cn = n, cd = d;
        #pragma unroll
        for (int o = 1; o < 32; o <<= 1) {   // inclusive scan over bins
            float vn = __shfl_up_sync(0xFFFFFFFFu, cn, o);
            float vd = __shfl_up_sync(0xFFFFFFFFu, cd, o);
            if (lane >= o) { cn += vn; cd += vd; }
        }
        float prec = cn / (1e-16f + cd);     // pDen / pNum
        float rec  = n / L;                  // num_per_bin / sum(labels)
        float term = (lane < NBIN) ? prec * rec : 0.0f;
        #pragma unroll
        for (int o = 16; o; o >>= 1) term += __shfl_xor_sync(0xFFFFFFFFu, term, o);
        if (lane == 0) s_ap[pass ? b1 : b0] = term;
    }
    __syncthreads();

    if (tid < 32) {
        float ap = (tid < NBATCH) ? s_ap[tid] : 0.0f;
        #pragma unroll
        for (int o = 16; o; o >>= 1) ap += __shfl_xor_sync(0xFFFFFFFFu, ap, o);
        if (tid == 0) out[0] = ap * (1.0f / (float)NBATCH);
    }
}

extern "C" void kernel_launch(void* const* d_in, const int* in_sizes, int n_in,
                              void* d_out, int out_size) {
    const float* qX   = (const float*)d_in[0];
    const float* dXs  = (const float*)d_in[1];
    const int*   labs = (const int*)d_in[2];
    float* out = (float*)d_out;

    const int B = in_sizes[0] / 128;   // 16
    const int N = in_sizes[2] / B;     // 50000

    dim3 grid(GRIDX, B, 1);
    qap_main_kernel<<<grid, 256>>>(qX, dXs, labs, N, out);
}

// round 16
// speedup vs baseline: 1.4320x; 1.4320x over previous
#include <cuda_runtime.h>
#include <cuda_bf16.h>

#define NBIN 25
#define INV_DELTA 12.0f          // (NBIN-1)/2
#define GRIDX 46                 // blocks per batch: 46*16=736 <= 148*5 -> single wave
#define NBATCH 16

// Per-(batch, block) partials; fully written by owner block each launch -> no zeroing.
__device__ float gp_num[NBATCH][GRIDX][32];
__device__ float gp_den[NBATCH][GRIDX][32];
__device__ float gp_lab[NBATCH][GRIDX];
// Per-batch AP and completion counter for the finalizer's mean step.
// atomicInc with limit NBATCH-1 wraps to 0 after the last block -> replay-safe.
__device__ float g_ap[NBATCH];
__device__ unsigned g_ctr = 0;

// Cap regs at 51 (5 blocks/SM guaranteed): hot loop needs ~44, no spill expected.
__global__ __launch_bounds__(256, 5) void qap_main_kernel(
    const float* __restrict__ qX,
    const float* __restrict__ dXs,
    const int* __restrict__ labels,
    int N)
{
    __shared__ float4 s_q[32];
    __shared__ float  s_num[8][32];
    __shared__ float  s_den[8][32];
    __shared__ float  s_lab[8];

    const int b    = blockIdx.y;
    const int tid  = threadIdx.x;
    const int lane = tid & 31;
    const int warp = tid >> 5;
    const int g    = lane >> 2;   // row-within-chunk 0..7
    const int s    = lane & 3;    // quarter-group sub-lane 0..3

    if (tid < 32) s_q[tid] = reinterpret_cast<const float4*>(qX + (long)b * 128)[tid];
    __syncthreads();

    // ||q||^2 (identical summation order on every thread)
    float qq = 0.0f;
    #pragma unroll
    for (int i = 0; i < 32; i++) {
        float4 v = s_q[i];
        qq += v.x * v.x + v.y * v.y + v.z * v.z + v.w * v.w;
    }
    const float qinv = 1.0f / fmaxf(sqrtf(qq), 1e-8f);

    const float4* __restrict__ dbase =
        reinterpret_cast<const float4*>(dXs) + ((long)b * N) * 32;
    const int* __restrict__ lab_b = labels + (long)b * N;

    const int warps_per_b = GRIDX * 8;
    const int wid = blockIdx.x * 8 + warp;
    const int nchunks = N >> 3;           // 8-row chunks of 4KB
    const float lane_f = (float)lane;

    float num_acc = 0.0f, den_acc = 0.0f, lab_acc = 0.0f;

    // === R9 main loop (best measured memory behavior), unchanged ===
    for (int c = wid; c < nchunks; c += warps_per_b) {
        const long row = (long)c * 8 + g;
        const float4* __restrict__ rp = dbase + row * 32 + s;

        // 8 independent strided loads (chunk = 4KB contiguous, fully coalesced)
        float4 d[8];
        #pragma unroll
        for (int i = 0; i < 8; i++) d[i] = rp[4 * i];

        // label for this group's row (lanes 0,4,...,28 -> 8 consecutive ints)
        int li = 0;
        if (s == 0) li = lab_b[row];

        float dot = 0.0f, dd = 0.0f;
        #pragma unroll
        for (int i = 0; i < 8; i++) {
            float4 qi = s_q[s + 4 * i];
            dot += d[i].x * qi.x + d[i].y * qi.y + d[i].z * qi.z + d[i].w * qi.w;
            dd  += d[i].x * d[i].x + d[i].y * d[i].y + d[i].z * d[i].z + d[i].w * d[i].w;
        }

        // reduce within group of 4 lanes (2 stages, 4 shuffles per 8 rows)
        dot += __shfl_xor_sync(0xFFFFFFFFu, dot, 1);
        dd  += __shfl_xor_sync(0xFFFFFFFFu, dd,  1);
        dot += __shfl_xor_sync(0xFFFFFFFFu, dot, 2);
        dd  += __shfl_xor_sync(0xFFFFFFFFu, dd,  2);

        // sim -> bin position t in [0,24]; pack label into sign bit (t==0 safe: -0.0)
        float sim = dot * qinv * rsqrtf(fmaxf(dd, 1e-16f));
        float t = fminf(fmaxf((1.0f - sim) * INV_DELTA, 0.0f), 24.0f);
        float u = __uint_as_float(__float_as_uint(t) | (((unsigned)li) << 31));

        // 8 broadcasts: whole warp applies triangular weights; lane owns bin lane.
        #pragma unroll
        for (int j = 0; j < 8; j++) {
            float uj = __shfl_sync(0xFFFFFFFFu, u, j * 4);
            unsigned ub = __float_as_uint(uj);
            float tj = __uint_as_float(ub & 0x7FFFFFFFu);
            float lj = (float)(ub >> 31);
            float w = fmaxf(1.0f - fabsf(tj - lane_f), 0.0f);
            den_acc += w;
            num_acc += w * lj;
            lab_acc += lj;
        }
    }

    // Tail rows (N % 8): warp-per-row on warp 0 (dead for N=50000)
    if ((N & 7) && wid == 0) {
        float4 qv = s_q[lane];
        for (long r = (long)nchunks * 8; r < N; r++) {
            float4 dv = dbase[r * 32 + lane];
            float dot = dv.x * qv.x + dv.y * qv.y + dv.z * qv.z + dv.w * qv.w;
            float dd  = dv.x * dv.x + dv.y * dv.y + dv.z * dv.z + dv.w * dv.w;
            #pragma unroll
            for (int o = 16; o; o >>= 1) {
                dot += __shfl_xor_sync(0xFFFFFFFFu, dot, o);
                dd  += __shfl_xor_sync(0xFFFFFFFFu, dd,  o);
            }
            float lbl = (float)lab_b[r];
            float sim = dot * qinv * rsqrtf(fmaxf(dd, 1e-16f));
            float t = fminf(fmaxf((1.0f - sim) * INV_DELTA, 0.0f), 24.0f);
            float w = fmaxf(1.0f - fabsf(t - lane_f), 0.0f);
            den_acc += w; num_acc += w * lbl; lab_acc += lbl;
        }
    }

    // Block reduction of per-warp partials (deterministic, no atomics).
    s_num[warp][lane] = num_acc;
    s_den[warp][lane] = den_acc;
    if (lane == 0) s_lab[warp] = lab_acc;
    __syncthreads();

    if (warp == 0) {
        float n = 0.0f, dsum = 0.0f;
        #pragma unroll
        for (int w2 = 0; w2 < 8; w2++) { n += s_num[w2][lane]; dsum += s_den[w2][lane]; }
        gp_num[b][blockIdx.x][lane] = n;
        gp_den[b][blockIdx.x][lane] = dsum;
        if (lane == 0) {
            float L = 0.0f;
            #pragma unroll
            for (int w2 = 0; w2 < 8; w2++) L += s_lab[w2];
            gp_lab[b][blockIdx.x] = L;
        }
    }
}

// 16 one-warp blocks: block b reduces batch b's partials; last block does the mean.
__global__ void qap_final_kernel(float* __restrict__ out) {
    const int b    = blockIdx.x;
    const int lane = threadIdx.x;

    float n = 0.0f, d = 0.0f, L = 0.0f;
    #pragma unroll 2
    for (int j = 0; j < GRIDX; j++) {   // coalesced 128B loads, interleaved streams
        n += gp_num[b][j][lane];
        d += gp_den[b][j][lane];
        L += gp_lab[b][j];
    }

    // inclusive scan across lanes (bins) for cumulative num/den
    float cn = n, cd = d;
    #pragma unroll
    for (int o = 1; o < 32; o <<= 1) {
        float vn = __shfl_up_sync(0xFFFFFFFFu, cn, o);
        float vd = __shfl_up_sync(0xFFFFFFFFu, cd, o);
        if (lane >= o) { cn += vn; cd += vd; }
    }

    float prec = cn / (1e-16f + cd);    // pDen / pNum
    float rec  = n / L;                 // num_per_bin / sum(labels)
    float term = (lane < NBIN) ? prec * rec : 0.0f;
    #pragma unroll
    for (int o = 16; o; o >>= 1) term += __shfl_xor_sync(0xFFFFFFFFu, term, o);

    int last = 0;
    if (lane == 0) {
        g_ap[b] = term;
        __threadfence();                                  // publish AP_b
        unsigned rank = atomicInc(&g_ctr, NBATCH - 1);    // wraps -> replay-safe
        last = (rank == NBATCH - 1);
    }
    last = __shfl_sync(0xFFFFFFFFu, last, 0);
    if (!last) return;

    __threadfence();   // acquire side
    float ap = (lane < NBATCH) ? g_ap[lane] : 0.0f;
    #pragma unroll
    for (int o = 16; o; o >>= 1) ap += __shfl_xor_sync(0xFFFFFFFFu, ap, o);
    if (lane == 0) out[0] = ap * (1.0f / (float)NBATCH);
}

extern "C" void kernel_launch(void* const* d_in, const int* in_sizes, int n_in,
                              void* d_out, int out_size) {
    const float* qX   = (const float*)d_in[0];
    const float* dXs  = (const float*)d_in[1];
    const int*   labs = (const int*)d_in[2];
    float* out = (float*)d_out;

    const int B = in_sizes[0] / 128;   // 16
    const int N = in_sizes[2] / B;     // 50000

    dim3 grid(GRIDX, B, 1);
    qap_main_kernel<<<grid, 256>>>(qX, dXs, labs, N);
    qap_final_kernel<<<NBATCH, 32>>>(out);
}

// round 17
// speedup vs baseline: 1.5180x; 1.0600x over previous
#include <cuda_runtime.h>
#include <cuda_bf16.h>

#define NBIN 25
#define INV_DELTA 12.0f          // (NBIN-1)/2
#define GRIDX 46                 // blocks per batch: 46*16=736 <= 148*5 -> single wave
#define NBATCH 16

// Per-(batch, block) partials; fully written by owner block each launch -> no zeroing.
__device__ float gp_num[NBATCH][GRIDX][32];
__device__ float gp_den[NBATCH][GRIDX][32];
__device__ float gp_lab[NBATCH][GRIDX];
// Per-batch AP and completion counter for the finalizer's mean step.
// atomicInc with limit NBATCH-1 wraps to 0 after the last block -> replay-safe.
__device__ float g_ap[NBATCH];
__device__ unsigned g_ctr = 0;

// Cap regs at 51 (5 blocks/SM guaranteed): hot loop needs ~44, no spill expected.
__global__ __launch_bounds__(256, 5) void qap_main_kernel(
    const float* __restrict__ qX,
    const float* __restrict__ dXs,
    const int* __restrict__ labels,
    int N)
{
    __shared__ float4 s_q[32];
    __shared__ float  s_num[8][32];
    __shared__ float  s_den[8][32];
    __shared__ float  s_lab[8];

    const int b    = blockIdx.y;
    const int tid  = threadIdx.x;
    const int lane = tid & 31;
    const int warp = tid >> 5;
    const int g    = lane >> 2;   // row-within-chunk 0..7
    const int s    = lane & 3;    // quarter-group sub-lane 0..3

    if (tid < 32) s_q[tid] = reinterpret_cast<const float4*>(qX + (long)b * 128)[tid];
    __syncthreads();

    // ||q||^2 (identical summation order on every thread)
    float qq = 0.0f;
    #pragma unroll
    for (int i = 0; i < 32; i++) {
        float4 v = s_q[i];
        qq += v.x * v.x + v.y * v.y + v.z * v.z + v.w * v.w;
    }
    const float qinv = 1.0f / fmaxf(sqrtf(qq), 1e-8f);

    const float4* __restrict__ dbase =
        reinterpret_cast<const float4*>(dXs) + ((long)b * N) * 32;
    const int* __restrict__ lab_b = labels + (long)b * N;

    const int warps_per_b = GRIDX * 8;
    const int wid = blockIdx.x * 8 + warp;
    const int nchunks = N >> 3;           // 8-row chunks of 4KB
    const float lane_f = (float)lane;

    float num_acc = 0.0f, den_acc = 0.0f, lab_acc = 0.0f;

    // === Known-best main loop (unchanged from R16) ===
    for (int c = wid; c < nchunks; c += warps_per_b) {
        const long row = (long)c * 8 + g;
        const float4* __restrict__ rp = dbase + row * 32 + s;

        // 8 independent strided loads (chunk = 4KB contiguous, fully coalesced)
        float4 d[8];
        #pragma unroll
        for (int i = 0; i < 8; i++) d[i] = rp[4 * i];

        // label for this group's row (lanes 0,4,...,28 -> 8 consecutive ints)
        int li = 0;
        if (s == 0) li = lab_b[row];

        float dot = 0.0f, dd = 0.0f;
        #pragma unroll
        for (int i = 0; i < 8; i++) {
            float4 qi = s_q[s + 4 * i];
            dot += d[i].x * qi.x + d[i].y * qi.y + d[i].z * qi.z + d[i].w * qi.w;
            dd  += d[i].x * d[i].x + d[i].y * d[i].y + d[i].z * d[i].z + d[i].w * d[i].w;
        }

        // reduce within group of 4 lanes (2 stages, 4 shuffles per 8 rows)
        dot += __shfl_xor_sync(0xFFFFFFFFu, dot, 1);
        dd  += __shfl_xor_sync(0xFFFFFFFFu, dd,  1);
        dot += __shfl_xor_sync(0xFFFFFFFFu, dot, 2);
        dd  += __shfl_xor_sync(0xFFFFFFFFu, dd,  2);

        // sim -> bin position t in [0,24]; pack label into sign bit (t==0 safe: -0.0)
        float sim = dot * qinv * rsqrtf(fmaxf(dd, 1e-16f));
        float t = fminf(fmaxf((1.0f - sim) * INV_DELTA, 0.0f), 24.0f);
        float u = __uint_as_float(__float_as_uint(t) | (((unsigned)li) << 31));

        // 8 broadcasts: whole warp applies triangular weights; lane owns bin lane.
        #pragma unroll
        for (int j = 0; j < 8; j++) {
            float uj = __shfl_sync(0xFFFFFFFFu, u, j * 4);
            unsigned ub = __float_as_uint(uj);
            float tj = __uint_as_float(ub & 0x7FFFFFFFu);
            float lj = (float)(ub >> 31);
            float w = fmaxf(1.0f - fabsf(tj - lane_f), 0.0f);
            den_acc += w;
            num_acc += w * lj;
            lab_acc += lj;
        }
    }

    // Tail rows (N % 8): warp-per-row on warp 0 (dead for N=50000)
    if ((N & 7) && wid == 0) {
        float4 qv = s_q[lane];
        for (long r = (long)nchunks * 8; r < N; r++) {
            float4 dv = dbase[r * 32 + lane];
            float dot = dv.x * qv.x + dv.y * qv.y + dv.z * qv.z + dv.w * qv.w;
            float dd  = dv.x * dv.x + dv.y * dv.y + dv.z * dv.z + dv.w * dv.w;
            #pragma unroll
            for (int o = 16; o; o >>= 1) {
                dot += __shfl_xor_sync(0xFFFFFFFFu, dot, o);
                dd  += __shfl_xor_sync(0xFFFFFFFFu, dd,  o);
            }
            float lbl = (float)lab_b[r];
            float sim = dot * qinv * rsqrtf(fmaxf(dd, 1e-16f));
            float t = fminf(fmaxf((1.0f - sim) * INV_DELTA, 0.0f), 24.0f);
            float w = fmaxf(1.0f - fabsf(t - lane_f), 0.0f);
            den_acc += w; num_acc += w * lbl; lab_acc += lbl;
        }
    }

    // Block reduction of per-warp partials (deterministic, no atomics).
    s_num[warp][lane] = num_acc;
    s_den[warp][lane] = den_acc;
    if (lane == 0) s_lab[warp] = lab_acc;
    __syncthreads();

    if (warp == 0) {
        float n = 0.0f, dsum = 0.0f;
        #pragma unroll
        for (int w2 = 0; w2 < 8; w2++) { n += s_num[w2][lane]; dsum += s_den[w2][lane]; }
        gp_num[b][blockIdx.x][lane] = n;
        gp_den[b][blockIdx.x][lane] = dsum;
        if (lane == 0) {
            float L = 0.0f;
            #pragma unroll
            for (int w2 = 0; w2 < 8; w2++) L += s_lab[w2];
            gp_lab[b][blockIdx.x] = L;
        }
    }
}

// 16 blocks x 256 threads: warp w covers partial-slices j = w, w+8, ... (<=6 each),
// giving 8x the warps and ~18 load streams per warp vs the R16 one-warp version.
__global__ __launch_bounds__(256) void qap_final_kernel(float* __restrict__ out) {
    __shared__ float sn[8][32];
    __shared__ float sd[8][32];
    __shared__ float sl[8];

    const int b    = blockIdx.x;
    const int lane = threadIdx.x & 31;
    const int warp = threadIdx.x >> 5;

    float n = 0.0f, d = 0.0f, L = 0.0f;
    for (int j = warp; j < GRIDX; j += 8) {
        n += gp_num[b][j][lane];
        d += gp_den[b][j][lane];
        L += gp_lab[b][j];     // same addr across lanes -> broadcast, 1 wavefront
    }
    sn[warp][lane] = n;
    sd[warp][lane] = d;
    if (lane == 0) sl[warp] = L;
    __syncthreads();

    if (warp != 0) return;

    n = 0.0f; d = 0.0f; L = 0.0f;
    #pragma unroll
    for (int w2 = 0; w2 < 8; w2++) {
        n += sn[w2][lane];
        d += sd[w2][lane];
        L += sl[w2];
    }

    // inclusive scan across lanes (bins) for cumulative num/den
    float cn = n, cd = d;
    #pragma unroll
    for (int o = 1; o < 32; o <<= 1) {
        float vn = __shfl_up_sync(0xFFFFFFFFu, cn, o);
        float vd = __shfl_up_sync(0xFFFFFFFFu, cd, o);
        if (lane >= o) { cn += vn; cd += vd; }
    }

    float prec = cn / (1e-16f + cd);    // pDen / pNum
    float rec  = n / L;                 // num_per_bin / sum(labels)
    float term = (lane < NBIN) ? prec * rec : 0.0f;
    #pragma unroll
    for (int o = 16; o; o >>= 1) term += __shfl_xor_sync(0xFFFFFFFFu, term, o);

    int last = 0;
    if (lane == 0) {
        g_ap[b] = term;
        __threadfence();                                  // publish AP_b
        unsigned rank = atomicInc(&g_ctr, NBATCH - 1);    // wraps -> replay-safe
        last = (rank == NBATCH - 1);
    }
    last = __shfl_sync(0xFFFFFFFFu, last, 0);
    if (!last) return;

    __threadfence();   // acquire side
    float ap = (lane < NBATCH) ? g_ap[lane] : 0.0f;
    #pragma unroll
    for (int o = 16; o; o >>= 1) ap += __shfl_xor_sync(0xFFFFFFFFu, ap, o);
    if (lane == 0) out[0] = ap * (1.0f / (float)NBATCH);
}

extern "C" void kernel_launch(void* const* d_in, const int* in_sizes, int n_in,
                              void* d_out, int out_size) {
    const float* qX   = (const float*)d_in[0];
    const float* dXs  = (const float*)d_in[1];
    const int*   labs = (const int*)d_in[2];
    float* out = (float*)d_out;

    const int B = in_sizes[0] / 128;   // 16
    const int N = in_sizes[2] / B;     // 50000

    dim3 grid(GRIDX, B, 1);
    qap_main_kernel<<<grid, 256>>>(qX, dXs, labs, N);
    qap_final_kernel<<<NBATCH, 256>>>(out);
}